// round 13
// baseline (speedup 1.0000x reference)
#include <cuda_runtime.h>
#include <cuda_fp16.h>
#include <cstdint>

#define N_NODES 8192
#define D_IN    128
#define D_OUT   128

// ---------------- device scratch (static, allocation-free) ----------------
__device__ float  g_dinv[N_NODES];
__device__ __half g_Bh[(size_t)D_OUT * N_NODES];       // B^T: [128][8192] K-major fp16, UNscaled

__device__ __forceinline__ uint32_t smem_u32(const void* p) {
    uint32_t a;
    asm("{ .reg .u64 t; cvta.to.shared.u64 t, %1; cvt.u32.u64 %0, t; }" : "=r"(a) : "l"(p));
    return a;
}
__device__ __forceinline__ void cp_async16(uint32_t dst, const void* src) {
    asm volatile("cp.async.cg.shared.global [%0], [%1], 16;" :: "r"(dst), "l"(src));
}
#define CP_COMMIT() asm volatile("cp.async.commit_group;" ::: "memory")

__device__ __forceinline__ uint32_t pack_h2(float lo, float hi) {
    uint32_t r;
    asm("cvt.rn.f16x2.f32 %0, %1, %2;" : "=r"(r) : "f"(hi), "f"(lo));
    return r;
}
__device__ __forceinline__ float2 lds_f2(uint32_t addr) {
    float2 v;
    asm volatile("ld.shared.v2.f32 {%0,%1}, [%2];" : "=f"(v.x), "=f"(v.y) : "r"(addr));
    return v;
}
__device__ __forceinline__ void mma_f16_16x8x16(float c[4], uint32_t a0, uint32_t a1, uint32_t a2, uint32_t a3,
                                                uint32_t b0, uint32_t b1) {
    asm volatile(
        "mma.sync.aligned.m16n8k16.row.col.f32.f16.f16.f32 "
        "{%0,%1,%2,%3}, {%4,%5,%6,%7}, {%8,%9}, {%0,%1,%2,%3};"
        : "+f"(c[0]), "+f"(c[1]), "+f"(c[2]), "+f"(c[3])
        : "r"(a0), "r"(a1), "r"(a2), "r"(a3), "r"(b0), "r"(b1));
}
__device__ __forceinline__ void ldsm_x4(uint32_t r[4], uint32_t addr) {
    asm volatile("ldmatrix.sync.aligned.m8n8.x4.shared.b16 {%0,%1,%2,%3}, [%4];"
        : "=r"(r[0]), "=r"(r[1]), "=r"(r[2]), "=r"(r[3]) : "r"(addr));
}

// ====== kernel 1 (merged): blocks [0,8192) row sums -> dinv ; blocks [8192,8448) fc ======
// fc computes B^T[o][j] = fp16( (V@W + b)[j][o] ) UNSCALED -> independent of dinv,
// so its compute hides under the rowsum blocks' DRAM-bound execution.
__global__ void pre_kernel(const float* __restrict__ A, const float* __restrict__ values,
                           const float* __restrict__ W, const float* __restrict__ bvec) {
    if (blockIdx.x < N_NODES) {
        // ---------------- row sum ----------------
        int row = blockIdx.x;
        const float4* arow = reinterpret_cast<const float4*>(A + (size_t)row * N_NODES);
        float4 v[8];
        #pragma unroll
        for (int i = 0; i < 8; ++i) v[i] = __ldcs(&arow[threadIdx.x + i * 256]);
        float s = 0.f;
        #pragma unroll
        for (int i = 0; i < 8; ++i) s += (v[i].x + v[i].y) + (v[i].z + v[i].w);
        #pragma unroll
        for (int o = 16; o; o >>= 1) s += __shfl_xor_sync(0xffffffffu, s, o);
        __shared__ float ws[8];
        if ((threadIdx.x & 31) == 0) ws[threadIdx.x >> 5] = s;
        __syncthreads();
        if (threadIdx.x < 8) {
            float t = ws[threadIdx.x];
            #pragma unroll
            for (int o = 4; o; o >>= 1) t += __shfl_xor_sync(0xffu, t, o);
            if (threadIdx.x == 0) g_dinv[row] = 1.0f / (sqrtf(t) + 1e-8f);
        }
    } else {
        // ---------------- fc (unscaled) ----------------
        int blk = blockIdx.x - N_NODES;
        int tid = threadIdx.x;
        int o = tid & 127;
        int half_idx = tid >> 7;
        int j0 = blk * 32 + half_idx * 16;
        float acc[16];
        #pragma unroll
        for (int i = 0; i < 16; ++i) acc[i] = 0.f;
        const float* vbase = values + (size_t)j0 * D_IN;
        for (int k = 0; k < D_IN; k += 4) {
            float w0 = W[(k + 0) * D_OUT + o];
            float w1 = W[(k + 1) * D_OUT + o];
            float w2 = W[(k + 2) * D_OUT + o];
            float w3 = W[(k + 3) * D_OUT + o];
            #pragma unroll
            for (int jj = 0; jj < 16; ++jj) {
                float4 v = *reinterpret_cast<const float4*>(vbase + jj * D_IN + k);
                acc[jj] = fmaf(v.x, w0, fmaf(v.y, w1, fmaf(v.z, w2, fmaf(v.w, w3, acc[jj]))));
            }
        }
        float bo = bvec[o];
        uint32_t packed[8];
        #pragma unroll
        for (int p = 0; p < 8; ++p)
            packed[p] = pack_h2(acc[2 * p] + bo, acc[2 * p + 1] + bo);
        uint4* dst = reinterpret_cast<uint4*>(g_Bh + (size_t)o * N_NODES + j0);
        dst[0] = make_uint4(packed[0], packed[1], packed[2], packed[3]);
        dst[1] = make_uint4(packed[4], packed[5], packed[6], packed[7]);
    }
}

// ===== kernel 2: balanced persistent GEMM; fp32 A, dinv[k]-scaled convert; fused flush =====
// Work unit = (rowblock 128 rows, BK=32 chunk): 64 x 256 = 16384 units over 148 CTAs.
// 8 warps 2m x 2n x 2k. A fragments scaled by dinv[col] at cvt; flush scaled by dinv[row].
#define BM 128
#define BK 32
#define STAGES 3
#define PITCH32 160                   // fp32 A rows: 128B data + 32B pad
#define PITCH16 80                    // fp16 B rows: 64B data + 16B pad
#define A32_BYTES (128 * PITCH32)     // 20480
#define B16_BYTES (128 * PITCH16)     // 10240
#define STAGE_BYTES (A32_BYTES + B16_BYTES)   // 30720
#define GEMM_SMEM (STAGES * STAGE_BYTES)      // 92160
#define NCTA 148

__device__ __forceinline__ void load_unit(int u, int buf, int tid,
                                          const float* __restrict__ A, uint32_t smem_base) {
    const int row_base = (u >> 8) * BM;
    const size_t kk = (size_t)(u & 255) * BK;
    const uint32_t sbase = smem_base + (uint32_t)buf * STAGE_BYTES;
    #pragma unroll
    for (int i = 0; i < 4; ++i) {         // A fp32: 1024 16B-chunks
        int c = tid + i * 256;
        int row = c >> 3, h = c & 7;
        cp_async16(sbase + (uint32_t)(row * PITCH32 + h * 16),
                   A + (size_t)(row_base + row) * N_NODES + kk + (size_t)h * 4);
    }
    #pragma unroll
    for (int i = 0; i < 2; ++i) {         // B fp16: 512 16B-chunks
        int c = tid + i * 256;
        int row = c >> 2, h = c & 3;
        cp_async16(sbase + A32_BYTES + (uint32_t)(row * PITCH16 + h * 16),
                   g_Bh + (size_t)row * N_NODES + kk + (size_t)h * 8);
    }
}

__global__ void __launch_bounds__(256, 1)
gemm_kernel(const float* __restrict__ A, float* __restrict__ out) {
    extern __shared__ float smem[];
    const uint32_t smem_base = smem_u32(smem);
    const int tid = threadIdx.x;
    const int lane = tid & 31;
    const int wid = tid >> 5;
    const int wm = wid & 1;               // 2 warps in m (64 rows)
    const int wn = (wid >> 1) & 1;        // 2 warps in n (64 cols)
    const int kh = wid >> 2;              // 2 warps in k (k16 halves of BK=32)
    const int g  = lane >> 2;
    const int tg = lane & 3;

    // balanced contiguous ranges: 104 CTAs x 111 units, 44 x 110
    const int cta = blockIdx.x;
    const int start = cta * 110 + min(cta, 104);
    const int count = 110 + (cta < 104 ? 1 : 0);

    const uint32_t aBase = (uint32_t)((wm * 64 + g) * PITCH32 + (kh * 16 + 2 * tg) * 4);
    const int bOff = (wn * 64 + ((lane >> 4) & 1) * 8 + (lane & 7)) * PITCH16
                   + ((lane >> 3) & 1) * 16 + kh * 32;
    const int dcol = kh * 16 + 2 * tg;    // dinv column offset within chunk

    float c[4][8][4];
    #pragma unroll
    for (int mi = 0; mi < 4; ++mi)
        #pragma unroll
        for (int ni = 0; ni < 8; ++ni)
            #pragma unroll
            for (int q = 0; q < 4; ++q) c[mi][ni][q] = 0.f;

    load_unit(start, 0, tid, A, smem_base);     CP_COMMIT();
    load_unit(start + 1, 1, tid, A, smem_base); CP_COMMIT();

    for (int j = 0; j < count; ++j) {
        const int u = start + j;

        // rowblock boundary: flush previous rowblock's accumulators (dinv-scaled atomics)
        if (j > 0 && (u & 255) == 0) {
            const int prb = (u - 1) >> 8;
            #pragma unroll
            for (int mi = 0; mi < 4; ++mi) {
                const int r0 = prb * BM + wm * 64 + mi * 16 + g;
                const float s0 = g_dinv[r0];
                const float s1 = g_dinv[r0 + 8];
                #pragma unroll
                for (int ni = 0; ni < 8; ++ni) {
                    const int col = wn * 64 + ni * 8 + 2 * tg;
                    atomicAdd(out + (size_t)r0 * D_OUT + col,           s0 * c[mi][ni][0]);
                    atomicAdd(out + (size_t)r0 * D_OUT + col + 1,       s0 * c[mi][ni][1]);
                    atomicAdd(out + (size_t)(r0 + 8) * D_OUT + col,     s1 * c[mi][ni][2]);
                    atomicAdd(out + (size_t)(r0 + 8) * D_OUT + col + 1, s1 * c[mi][ni][3]);
                    c[mi][ni][0] = c[mi][ni][1] = c[mi][ni][2] = c[mi][ni][3] = 0.f;
                }
            }
        }

        asm volatile("cp.async.wait_group %0;" :: "n"(STAGES - 2) : "memory");
        __syncthreads();

        if (j + 2 < count) load_unit(u + 2, (j + 2) % STAGES, tid, A, smem_base);
        CP_COMMIT();

        // dinv for this unit's k-chunk columns
        const int k0 = (u & 255) * BK;
        const float2 d01 = *reinterpret_cast<const float2*>(g_dinv + k0 + dcol);
        const float2 d89 = *reinterpret_cast<const float2*>(g_dinv + k0 + dcol + 8);

        const uint32_t smA = smem_base + (uint32_t)(j % STAGES) * STAGE_BYTES;
        const uint32_t smB = smA + A32_BYTES;

        uint32_t a[4][4];
        #pragma unroll
        for (int mi = 0; mi < 4; ++mi) {
            const uint32_t r0 = smA + aBase + (uint32_t)(mi * 16 * PITCH32);
            float2 v0 = lds_f2(r0);
            float2 v1 = lds_f2(r0 + 8 * PITCH32);
            float2 v2 = lds_f2(r0 + 32);
            float2 v3 = lds_f2(r0 + 8 * PITCH32 + 32);
            a[mi][0] = pack_h2(v0.x * d01.x, v0.y * d01.y);
            a[mi][1] = pack_h2(v1.x * d01.x, v1.y * d01.y);
            a[mi][2] = pack_h2(v2.x * d89.x, v2.y * d89.y);
            a[mi][3] = pack_h2(v3.x * d89.x, v3.y * d89.y);
        }
        uint32_t b[4][4];
        #pragma unroll
        for (int cb = 0; cb < 4; ++cb)
            ldsm_x4(b[cb], smB + (uint32_t)(bOff + cb * 16 * PITCH16));

        #pragma unroll
        for (int mi = 0; mi < 4; ++mi) {
            #pragma unroll
            for (int ni = 0; ni < 8; ++ni) {
                mma_f16_16x8x16(c[mi][ni], a[mi][0], a[mi][1], a[mi][2], a[mi][3],
                                b[ni >> 1][(ni & 1) * 2], b[ni >> 1][(ni & 1) * 2 + 1]);
            }
        }
    }

    // final flush
    {
        const int prb = (start + count - 1) >> 8;
        #pragma unroll
        for (int mi = 0; mi < 4; ++mi) {
            const int r0 = prb * BM + wm * 64 + mi * 16 + g;
            const float s0 = g_dinv[r0];
            const float s1 = g_dinv[r0 + 8];
            #pragma unroll
            for (int ni = 0; ni < 8; ++ni) {
                const int col = wn * 64 + ni * 8 + 2 * tg;
                atomicAdd(out + (size_t)r0 * D_OUT + col,           s0 * c[mi][ni][0]);
                atomicAdd(out + (size_t)r0 * D_OUT + col + 1,       s0 * c[mi][ni][1]);
                atomicAdd(out + (size_t)(r0 + 8) * D_OUT + col,     s1 * c[mi][ni][2]);
                atomicAdd(out + (size_t)(r0 + 8) * D_OUT + col + 1, s1 * c[mi][ni][3]);
            }
        }
    }
}

// ================= launch =================
extern "C" void kernel_launch(void* const* d_in, const int* in_sizes, int n_in,
                              void* d_out, int out_size) {
    const float* values = (const float*)d_in[0];
    const float* A      = (const float*)d_in[1];
    const float* W      = (const float*)d_in[2];
    const float* b      = (const float*)d_in[3];
    float* out = (float*)d_out;

    cudaMemsetAsync(out, 0, (size_t)out_size * sizeof(float));
    pre_kernel<<<N_NODES + N_NODES / 32, 256>>>(A, values, W, b);
    cudaFuncSetAttribute(gemm_kernel, cudaFuncAttributeMaxDynamicSharedMemorySize, GEMM_SMEM);
    gemm_kernel<<<NCTA, 256, GEMM_SMEM>>>(A, out);
}

// round 15
// speedup vs baseline: 1.3525x; 1.3525x over previous
#include <cuda_runtime.h>
#include <cuda_fp16.h>
#include <cstdint>

#define N_NODES 8192
#define D_IN    128
#define D_OUT   128

// ---------------- device scratch (static, allocation-free) ----------------
__device__ float  g_dinv[N_NODES];
__device__ __half g_Bh[(size_t)D_OUT * N_NODES];       // B^T: [128][8192] K-major fp16

__device__ __forceinline__ uint32_t smem_u32(const void* p) {
    uint32_t a;
    asm("{ .reg .u64 t; cvta.to.shared.u64 t, %1; cvt.u32.u64 %0, t; }" : "=r"(a) : "l"(p));
    return a;
}
__device__ __forceinline__ void cp_async16(uint32_t dst, const void* src) {
    asm volatile("cp.async.cg.shared.global [%0], [%1], 16;" :: "r"(dst), "l"(src));
}
#define CP_COMMIT() asm volatile("cp.async.commit_group;" ::: "memory")

__device__ __forceinline__ uint32_t pack_h2(float lo, float hi) {
    uint32_t r;
    asm("cvt.rn.f16x2.f32 %0, %1, %2;" : "=r"(r) : "f"(hi), "f"(lo));
    return r;
}
__device__ __forceinline__ float2 lds_f2(uint32_t addr) {
    float2 v;
    asm volatile("ld.shared.v2.f32 {%0,%1}, [%2];" : "=f"(v.x), "=f"(v.y) : "r"(addr));
    return v;
}
__device__ __forceinline__ void mma_f16_16x8x16(float c[4], uint32_t a0, uint32_t a1, uint32_t a2, uint32_t a3,
                                                uint32_t b0, uint32_t b1) {
    asm volatile(
        "mma.sync.aligned.m16n8k16.row.col.f32.f16.f16.f32 "
        "{%0,%1,%2,%3}, {%4,%5,%6,%7}, {%8,%9}, {%0,%1,%2,%3};"
        : "+f"(c[0]), "+f"(c[1]), "+f"(c[2]), "+f"(c[3])
        : "r"(a0), "r"(a1), "r"(a2), "r"(a3), "r"(b0), "r"(b1));
}
__device__ __forceinline__ void ldsm_x4(uint32_t r[4], uint32_t addr) {
    asm volatile("ldmatrix.sync.aligned.m8n8.x4.shared.b16 {%0,%1,%2,%3}, [%4];"
        : "=r"(r[0]), "=r"(r[1]), "=r"(r[2]), "=r"(r[3]) : "r"(addr));
}

// ====== kernel 1 (merged, reg-capped): blocks [0,8192) rowsum ; [8192,8704) fc ======
// __launch_bounds__(256, 6) caps regs ~40 so the fc branch cannot deflate rowsum occupancy.
// fc branch: 512 blocks, 8 accumulators/thread (register-light), emits UNscaled B.
__global__ void __launch_bounds__(256, 6)
pre_kernel(const float* __restrict__ A, const float* __restrict__ values,
           const float* __restrict__ W, const float* __restrict__ bvec) {
    if (blockIdx.x < N_NODES) {
        // ---------------- row sum ----------------
        int row = blockIdx.x;
        const float4* arow = reinterpret_cast<const float4*>(A + (size_t)row * N_NODES);
        float4 v[8];
        #pragma unroll
        for (int i = 0; i < 8; ++i) v[i] = __ldcs(&arow[threadIdx.x + i * 256]);
        float s = 0.f;
        #pragma unroll
        for (int i = 0; i < 8; ++i) s += (v[i].x + v[i].y) + (v[i].z + v[i].w);
        #pragma unroll
        for (int o = 16; o; o >>= 1) s += __shfl_xor_sync(0xffffffffu, s, o);
        __shared__ float ws[8];
        if ((threadIdx.x & 31) == 0) ws[threadIdx.x >> 5] = s;
        __syncthreads();
        if (threadIdx.x < 8) {
            float t = ws[threadIdx.x];
            #pragma unroll
            for (int o = 4; o; o >>= 1) t += __shfl_xor_sync(0xffu, t, o);
            if (threadIdx.x == 0) g_dinv[row] = 1.0f / (sqrtf(t) + 1e-8f);
        }
    } else {
        // ---------------- fc (unscaled, register-light) ----------------
        int blk = blockIdx.x - N_NODES;           // 0..511
        int tid = threadIdx.x;
        int o = tid & 127;
        int half_idx = tid >> 7;
        int j0 = blk * 16 + half_idx * 8;
        float acc[8];
        #pragma unroll
        for (int i = 0; i < 8; ++i) acc[i] = 0.f;
        const float* vbase = values + (size_t)j0 * D_IN;
        for (int k = 0; k < D_IN; k += 4) {
            float w0 = W[(k + 0) * D_OUT + o];
            float w1 = W[(k + 1) * D_OUT + o];
            float w2 = W[(k + 2) * D_OUT + o];
            float w3 = W[(k + 3) * D_OUT + o];
            #pragma unroll
            for (int jj = 0; jj < 8; ++jj) {
                float4 v = *reinterpret_cast<const float4*>(vbase + jj * D_IN + k);
                acc[jj] = fmaf(v.x, w0, fmaf(v.y, w1, fmaf(v.z, w2, fmaf(v.w, w3, acc[jj]))));
            }
        }
        float bo = bvec[o];
        uint32_t packed[4];
        #pragma unroll
        for (int p = 0; p < 4; ++p)
            packed[p] = pack_h2(acc[2 * p] + bo, acc[2 * p + 1] + bo);
        *reinterpret_cast<uint4*>(g_Bh + (size_t)o * N_NODES + j0) =
            make_uint4(packed[0], packed[1], packed[2], packed[3]);
    }
}

// ====== kernel 2: g_Bh[o][j] *= dinv[j]  (fp32-domain multiply; 2 MB ~1.5us) ======
// g_Bh rows are 8192 halves = 4096 half2. Column of half2 index g: j = (g & 4095) * 2.
__global__ void scaleB_kernel() {
    int gid = blockIdx.x * 256 + threadIdx.x;     // 0..131071, each handles 4 half2
    int g0 = gid * 4;
    int j0 = (g0 & 4095) * 2;                     // column of first half
    const float4 d0 = *reinterpret_cast<const float4*>(g_dinv + j0);
    const float4 d1 = *reinterpret_cast<const float4*>(g_dinv + j0 + 4);
    __half2* p = reinterpret_cast<__half2*>(g_Bh) + g0;
    __half2 v0 = p[0], v1 = p[1], v2 = p[2], v3 = p[3];
    float2 f0 = __half22float2(v0), f1 = __half22float2(v1);
    float2 f2 = __half22float2(v2), f3 = __half22float2(v3);
    p[0] = __floats2half2_rn(f0.x * d0.x, f0.y * d0.y);
    p[1] = __floats2half2_rn(f1.x * d0.z, f1.y * d0.w);
    p[2] = __floats2half2_rn(f2.x * d1.x, f2.y * d1.y);
    p[3] = __floats2half2_rn(f3.x * d1.z, f3.y * d1.w);
}

// ===== kernel 3: balanced persistent GEMM (R10 verbatim) =====
#define BM 128
#define BK 32
#define STAGES 3
#define PITCH32 160
#define PITCH16 80
#define A32_BYTES (128 * PITCH32)
#define B16_BYTES (128 * PITCH16)
#define STAGE_BYTES (A32_BYTES + B16_BYTES)
#define GEMM_SMEM (STAGES * STAGE_BYTES)
#define NCTA 148

__device__ __forceinline__ void load_unit(int u, int buf, int tid,
                                          const float* __restrict__ A, uint32_t smem_base) {
    const int row_base = (u >> 8) * BM;
    const size_t kk = (size_t)(u & 255) * BK;
    const uint32_t sbase = smem_base + (uint32_t)buf * STAGE_BYTES;
    #pragma unroll
    for (int i = 0; i < 4; ++i) {
        int c = tid + i * 256;
        int row = c >> 3, h = c & 7;
        cp_async16(sbase + (uint32_t)(row * PITCH32 + h * 16),
                   A + (size_t)(row_base + row) * N_NODES + kk + (size_t)h * 4);
    }
    #pragma unroll
    for (int i = 0; i < 2; ++i) {
        int c = tid + i * 256;
        int row = c >> 2, h = c & 3;
        cp_async16(sbase + A32_BYTES + (uint32_t)(row * PITCH16 + h * 16),
                   g_Bh + (size_t)row * N_NODES + kk + (size_t)h * 8);
    }
}

__global__ void __launch_bounds__(256, 1)
gemm_kernel(const float* __restrict__ A, float* __restrict__ out) {
    extern __shared__ float smem[];
    const uint32_t smem_base = smem_u32(smem);
    const int tid = threadIdx.x;
    const int lane = tid & 31;
    const int wid = tid >> 5;
    const int wm = wid & 1;
    const int wn = (wid >> 1) & 1;
    const int kh = wid >> 2;
    const int g  = lane >> 2;
    const int tg = lane & 3;

    const int cta = blockIdx.x;
    const int start = cta * 110 + min(cta, 104);
    const int count = 110 + (cta < 104 ? 1 : 0);

    const uint32_t aBase = (uint32_t)((wm * 64 + g) * PITCH32 + (kh * 16 + 2 * tg) * 4);
    const int bOff = (wn * 64 + ((lane >> 4) & 1) * 8 + (lane & 7)) * PITCH16
                   + ((lane >> 3) & 1) * 16 + kh * 32;

    float c[4][8][4];
    #pragma unroll
    for (int mi = 0; mi < 4; ++mi)
        #pragma unroll
        for (int ni = 0; ni < 8; ++ni)
            #pragma unroll
            for (int q = 0; q < 4; ++q) c[mi][ni][q] = 0.f;

    load_unit(start, 0, tid, A, smem_base);     CP_COMMIT();
    load_unit(start + 1, 1, tid, A, smem_base); CP_COMMIT();

    for (int j = 0; j < count; ++j) {
        const int u = start + j;

        if (j > 0 && (u & 255) == 0) {
            const int prb = (u - 1) >> 8;
            #pragma unroll
            for (int mi = 0; mi < 4; ++mi) {
                const int r0 = prb * BM + wm * 64 + mi * 16 + g;
                const float s0 = g_dinv[r0];
                const float s1 = g_dinv[r0 + 8];
                #pragma unroll
                for (int ni = 0; ni < 8; ++ni) {
                    const int col = wn * 64 + ni * 8 + 2 * tg;
                    atomicAdd(out + (size_t)r0 * D_OUT + col,           s0 * c[mi][ni][0]);
                    atomicAdd(out + (size_t)r0 * D_OUT + col + 1,       s0 * c[mi][ni][1]);
                    atomicAdd(out + (size_t)(r0 + 8) * D_OUT + col,     s1 * c[mi][ni][2]);
                    atomicAdd(out + (size_t)(r0 + 8) * D_OUT + col + 1, s1 * c[mi][ni][3]);
                    c[mi][ni][0] = c[mi][ni][1] = c[mi][ni][2] = c[mi][ni][3] = 0.f;
                }
            }
        }

        asm volatile("cp.async.wait_group %0;" :: "n"(STAGES - 2) : "memory");
        __syncthreads();

        if (j + 2 < count) load_unit(u + 2, (j + 2) % STAGES, tid, A, smem_base);
        CP_COMMIT();

        const uint32_t smA = smem_base + (uint32_t)(j % STAGES) * STAGE_BYTES;
        const uint32_t smB = smA + A32_BYTES;

        uint32_t a[4][4];
        #pragma unroll
        for (int mi = 0; mi < 4; ++mi) {
            const uint32_t r0 = smA + aBase + (uint32_t)(mi * 16 * PITCH32);
            float2 v0 = lds_f2(r0);
            float2 v1 = lds_f2(r0 + 8 * PITCH32);
            float2 v2 = lds_f2(r0 + 32);
            float2 v3 = lds_f2(r0 + 8 * PITCH32 + 32);
            a[mi][0] = pack_h2(v0.x, v0.y);
            a[mi][1] = pack_h2(v1.x, v1.y);
            a[mi][2] = pack_h2(v2.x, v2.y);
            a[mi][3] = pack_h2(v3.x, v3.y);
        }
        uint32_t b[4][4];
        #pragma unroll
        for (int cb = 0; cb < 4; ++cb)
            ldsm_x4(b[cb], smB + (uint32_t)(bOff + cb * 16 * PITCH16));

        #pragma unroll
        for (int mi = 0; mi < 4; ++mi) {
            #pragma unroll
            for (int ni = 0; ni < 8; ++ni) {
                mma_f16_16x8x16(c[mi][ni], a[mi][0], a[mi][1], a[mi][2], a[mi][3],
                                b[ni >> 1][(ni & 1) * 2], b[ni >> 1][(ni & 1) * 2 + 1]);
            }
        }
    }

    {
        const int prb = (start + count - 1) >> 8;
        #pragma unroll
        for (int mi = 0; mi < 4; ++mi) {
            const int r0 = prb * BM + wm * 64 + mi * 16 + g;
            const float s0 = g_dinv[r0];
            const float s1 = g_dinv[r0 + 8];
            #pragma unroll
            for (int ni = 0; ni < 8; ++ni) {
                const int col = wn * 64 + ni * 8 + 2 * tg;
                atomicAdd(out + (size_t)r0 * D_OUT + col,           s0 * c[mi][ni][0]);
                atomicAdd(out + (size_t)r0 * D_OUT + col + 1,       s0 * c[mi][ni][1]);
                atomicAdd(out + (size_t)(r0 + 8) * D_OUT + col,     s1 * c[mi][ni][2]);
                atomicAdd(out + (size_t)(r0 + 8) * D_OUT + col + 1, s1 * c[mi][ni][3]);
            }
        }
    }
}

// ================= launch =================
extern "C" void kernel_launch(void* const* d_in, const int* in_sizes, int n_in,
                              void* d_out, int out_size) {
    const float* values = (const float*)d_in[0];
    const float* A      = (const float*)d_in[1];
    const float* W      = (const float*)d_in[2];
    const float* b      = (const float*)d_in[3];
    float* out = (float*)d_out;

    cudaMemsetAsync(out, 0, (size_t)out_size * sizeof(float));
    pre_kernel<<<N_NODES + 512, 256>>>(A, values, W, b);
    scaleB_kernel<<<512, 256>>>();
    cudaFuncSetAttribute(gemm_kernel, cudaFuncAttributeMaxDynamicSharedMemorySize, GEMM_SMEM);
    gemm_kernel<<<NCTA, 256, GEMM_SMEM>>>(A, out);
}

// round 17
// speedup vs baseline: 1.5144x; 1.1197x over previous
#include <cuda_runtime.h>
#include <cuda_fp16.h>
#include <cstdint>

#define N_NODES 8192
#define D_IN    128
#define D_OUT   128

// ---------------- device scratch (static, allocation-free) ----------------
__device__ float  g_dinv[N_NODES];
__device__ __half g_Bh[(size_t)D_OUT * N_NODES];       // B^T: [128][8192] K-major fp16, dinv-scaled

__device__ __forceinline__ uint32_t smem_u32(const void* p) {
    uint32_t a;
    asm("{ .reg .u64 t; cvta.to.shared.u64 t, %1; cvt.u32.u64 %0, t; }" : "=r"(a) : "l"(p));
    return a;
}
__device__ __forceinline__ void cp_async16(uint32_t dst, const void* src) {
    asm volatile("cp.async.cg.shared.global [%0], [%1], 16;" :: "r"(dst), "l"(src));
}
#define CP_COMMIT() asm volatile("cp.async.commit_group;" ::: "memory")

__device__ __forceinline__ uint32_t pack_h2(float lo, float hi) {
    uint32_t r;
    asm("cvt.rn.f16x2.f32 %0, %1, %2;" : "=r"(r) : "f"(hi), "f"(lo));
    return r;
}
__device__ __forceinline__ float2 lds_f2(uint32_t addr) {
    float2 v;
    asm volatile("ld.shared.v2.f32 {%0,%1}, [%2];" : "=f"(v.x), "=f"(v.y) : "r"(addr));
    return v;
}
__device__ __forceinline__ void mma_f16_16x8x16(float c[4], uint32_t a0, uint32_t a1, uint32_t a2, uint32_t a3,
                                                uint32_t b0, uint32_t b1) {
    asm volatile(
        "mma.sync.aligned.m16n8k16.row.col.f32.f16.f16.f32 "
        "{%0,%1,%2,%3}, {%4,%5,%6,%7}, {%8,%9}, {%0,%1,%2,%3};"
        : "+f"(c[0]), "+f"(c[1]), "+f"(c[2]), "+f"(c[3])
        : "r"(a0), "r"(a1), "r"(a2), "r"(a3), "r"(b0), "r"(b1));
}
__device__ __forceinline__ void ldsm_x4(uint32_t r[4], uint32_t addr) {
    asm volatile("ldmatrix.sync.aligned.m8n8.x4.shared.b16 {%0,%1,%2,%3}, [%4];"
        : "=r"(r[0]), "=r"(r[1]), "=r"(r[2]), "=r"(r[3]) : "r"(addr));
}

// ================= kernel 1: row sums -> dinv (read-only) =================
__global__ void rowsum_kernel(const float* __restrict__ A) {
    int row = blockIdx.x;
    const float4* arow = reinterpret_cast<const float4*>(A + (size_t)row * N_NODES);
    float4 v[8];
    #pragma unroll
    for (int i = 0; i < 8; ++i) v[i] = __ldcs(&arow[threadIdx.x + i * 256]);
    float s = 0.f;
    #pragma unroll
    for (int i = 0; i < 8; ++i) s += (v[i].x + v[i].y) + (v[i].z + v[i].w);
    #pragma unroll
    for (int o = 16; o; o >>= 1) s += __shfl_xor_sync(0xffffffffu, s, o);
    __shared__ float ws[8];
    if ((threadIdx.x & 31) == 0) ws[threadIdx.x >> 5] = s;
    __syncthreads();
    if (threadIdx.x < 8) {
        float t = ws[threadIdx.x];
        #pragma unroll
        for (int o = 4; o; o >>= 1) t += __shfl_xor_sync(0xffu, t, o);
        if (threadIdx.x == 0) g_dinv[row] = 1.0f / (sqrtf(t) + 1e-8f);
    }
}

// ============ kernel 2: B^T[o][j] = fp16( dinv[j] * (V@W + b)[j][o] ) ============
__global__ void fc_kernel(const float* __restrict__ values, const float* __restrict__ W,
                          const float* __restrict__ bvec) {
    int tid = threadIdx.x;
    int o = tid & 127;
    int half_idx = tid >> 7;
    int j0 = blockIdx.x * 32 + half_idx * 16;
    float acc[16];
    #pragma unroll
    for (int i = 0; i < 16; ++i) acc[i] = 0.f;
    const float* vbase = values + (size_t)j0 * D_IN;
    for (int k = 0; k < D_IN; k += 4) {
        float w0 = W[(k + 0) * D_OUT + o];
        float w1 = W[(k + 1) * D_OUT + o];
        float w2 = W[(k + 2) * D_OUT + o];
        float w3 = W[(k + 3) * D_OUT + o];
        #pragma unroll
        for (int jj = 0; jj < 16; ++jj) {
            float4 v = *reinterpret_cast<const float4*>(vbase + jj * D_IN + k);
            acc[jj] = fmaf(v.x, w0, fmaf(v.y, w1, fmaf(v.z, w2, fmaf(v.w, w3, acc[jj]))));
        }
    }
    float bo = bvec[o];
    uint32_t packed[8];
    #pragma unroll
    for (int p = 0; p < 8; ++p) {
        float y0 = (acc[2 * p]     + bo) * g_dinv[j0 + 2 * p];
        float y1 = (acc[2 * p + 1] + bo) * g_dinv[j0 + 2 * p + 1];
        packed[p] = pack_h2(y0, y1);
    }
    uint4* dst = reinterpret_cast<uint4*>(g_Bh + (size_t)o * N_NODES + j0);
    dst[0] = make_uint4(packed[0], packed[1], packed[2], packed[3]);
    dst[1] = make_uint4(packed[4], packed[5], packed[6], packed[7]);
}

// ===== kernel 3: balanced persistent GEMM, BK=64 (R10 structure, halved iterations) =====
// Work unit = (rowblock 128 rows, BK=64 chunk): 64 x 128 = 8192 units over 148 CTAs.
// 8 warps 2m x 2n x 2k; each kh warp handles k16 tiles {kh, kh+2} per unit.
#define BM 128
#define BK 64
#define STAGES 3
#define PITCH32 288                   // fp32 A rows: 256B data + 32B pad (72 w ≡ 8 mod 32)
#define PITCH16 144                   // fp16 B rows: 128B data + 16B pad (36 w ≡ 4 mod 32)
#define A32_BYTES (128 * PITCH32)     // 36864
#define B16_BYTES (128 * PITCH16)     // 18432
#define STAGE_BYTES (A32_BYTES + B16_BYTES)   // 55296
#define GEMM_SMEM (STAGES * STAGE_BYTES)      // 165888
#define NCTA 148

__device__ __forceinline__ void load_unit(int u, int buf, int tid,
                                          const float* __restrict__ A, uint32_t smem_base) {
    const int row_base = (u >> 7) * BM;
    const size_t kk = (size_t)(u & 127) * BK;
    const uint32_t sbase = smem_base + (uint32_t)buf * STAGE_BYTES;
    #pragma unroll
    for (int i = 0; i < 8; ++i) {         // A fp32: 128 rows x 16 16B-chunks
        int c = tid + i * 256;
        int row = c >> 4, h = c & 15;
        cp_async16(sbase + (uint32_t)(row * PITCH32 + h * 16),
                   A + (size_t)(row_base + row) * N_NODES + kk + (size_t)h * 4);
    }
    #pragma unroll
    for (int i = 0; i < 4; ++i) {         // B fp16: 128 rows x 8 16B-chunks
        int c = tid + i * 256;
        int row = c >> 3, h = c & 7;
        cp_async16(sbase + A32_BYTES + (uint32_t)(row * PITCH16 + h * 16),
                   g_Bh + (size_t)row * N_NODES + kk + (size_t)h * 8);
    }
}

__global__ void __launch_bounds__(256, 1)
gemm_kernel(const float* __restrict__ A, float* __restrict__ out) {
    extern __shared__ float smem[];
    const uint32_t smem_base = smem_u32(smem);
    const int tid = threadIdx.x;
    const int lane = tid & 31;
    const int wid = tid >> 5;
    const int wm = wid & 1;               // 2 warps in m (64 rows)
    const int wn = (wid >> 1) & 1;        // 2 warps in n (64 cols)
    const int kh = wid >> 2;              // 2 warps in k
    const int g  = lane >> 2;
    const int tg = lane & 3;

    // balanced contiguous ranges: 52 CTAs x 56 units, 96 x 55
    const int cta = blockIdx.x;
    const int start = cta * 55 + min(cta, 52);
    const int count = 55 + (cta < 52 ? 1 : 0);

    const uint32_t aBase = (uint32_t)((wm * 64 + g) * PITCH32 + tg * 8);
    const uint32_t bBase = (uint32_t)((wn * 64 + ((lane >> 4) & 1) * 8 + (lane & 7)) * PITCH16
                                      + ((lane >> 3) & 1) * 16);

    float c[4][8][4];
    #pragma unroll
    for (int mi = 0; mi < 4; ++mi)
        #pragma unroll
        for (int ni = 0; ni < 8; ++ni)
            #pragma unroll
            for (int q = 0; q < 4; ++q) c[mi][ni][q] = 0.f;

    load_unit(start, 0, tid, A, smem_base);     CP_COMMIT();
    load_unit(start + 1, 1, tid, A, smem_base); CP_COMMIT();

    for (int j = 0; j < count; ++j) {
        const int u = start + j;

        // rowblock boundary: flush previous rowblock's accumulators (dinv-scaled atomics)
        if (j > 0 && (u & 127) == 0) {
            const int prb = (u - 1) >> 7;
            #pragma unroll
            for (int mi = 0; mi < 4; ++mi) {
                const int r0 = prb * BM + wm * 64 + mi * 16 + g;
                const float s0 = g_dinv[r0];
                const float s1 = g_dinv[r0 + 8];
                #pragma unroll
                for (int ni = 0; ni < 8; ++ni) {
                    const int col = wn * 64 + ni * 8 + 2 * tg;
                    atomicAdd(out + (size_t)r0 * D_OUT + col,           s0 * c[mi][ni][0]);
                    atomicAdd(out + (size_t)r0 * D_OUT + col + 1,       s0 * c[mi][ni][1]);
                    atomicAdd(out + (size_t)(r0 + 8) * D_OUT + col,     s1 * c[mi][ni][2]);
                    atomicAdd(out + (size_t)(r0 + 8) * D_OUT + col + 1, s1 * c[mi][ni][3]);
                    c[mi][ni][0] = c[mi][ni][1] = c[mi][ni][2] = c[mi][ni][3] = 0.f;
                }
            }
        }

        asm volatile("cp.async.wait_group %0;" :: "n"(STAGES - 2) : "memory");
        __syncthreads();

        if (j + 2 < count) load_unit(u + 2, (j + 2) % STAGES, tid, A, smem_base);
        CP_COMMIT();

        const uint32_t smA = smem_base + (uint32_t)(j % STAGES) * STAGE_BYTES;
        const uint32_t smB = smA + A32_BYTES;

        #pragma unroll
        for (int ks = 0; ks < 2; ++ks) {
            const int k16 = kh + 2 * ks;          // kh warp covers tiles kh, kh+2
            const uint32_t aK = (uint32_t)(k16 * 64);    // fp32 bytes
            const uint32_t bK = (uint32_t)(k16 * 32);    // fp16 bytes

            uint32_t a[4][4];
            #pragma unroll
            for (int mi = 0; mi < 4; ++mi) {
                const uint32_t r0 = smA + aBase + aK + (uint32_t)(mi * 16 * PITCH32);
                float2 v0 = lds_f2(r0);
                float2 v1 = lds_f2(r0 + 8 * PITCH32);
                float2 v2 = lds_f2(r0 + 32);
                float2 v3 = lds_f2(r0 + 8 * PITCH32 + 32);
                a[mi][0] = pack_h2(v0.x, v0.y);
                a[mi][1] = pack_h2(v1.x, v1.y);
                a[mi][2] = pack_h2(v2.x, v2.y);
                a[mi][3] = pack_h2(v3.x, v3.y);
            }
            uint32_t b[4][4];
            #pragma unroll
            for (int cb = 0; cb < 4; ++cb)
                ldsm_x4(b[cb], smB + bBase + bK + (uint32_t)(cb * 16 * PITCH16));

            #pragma unroll
            for (int mi = 0; mi < 4; ++mi) {
                #pragma unroll
                for (int ni = 0; ni < 8; ++ni) {
                    mma_f16_16x8x16(c[mi][ni], a[mi][0], a[mi][1], a[mi][2], a[mi][3],
                                    b[ni >> 1][(ni & 1) * 2], b[ni >> 1][(ni & 1) * 2 + 1]);
                }
            }
        }
    }

    // final flush
    {
        const int prb = (start + count - 1) >> 7;
        #pragma unroll
        for (int mi = 0; mi < 4; ++mi) {
            const int r0 = prb * BM + wm * 64 + mi * 16 + g;
            const float s0 = g_dinv[r0];
            const float s1 = g_dinv[r0 + 8];
            #pragma unroll
            for (int ni = 0; ni < 8; ++ni) {
                const int col = wn * 64 + ni * 8 + 2 * tg;
                atomicAdd(out + (size_t)r0 * D_OUT + col,           s0 * c[mi][ni][0]);
                atomicAdd(out + (size_t)r0 * D_OUT + col + 1,       s0 * c[mi][ni][1]);
                atomicAdd(out + (size_t)(r0 + 8) * D_OUT + col,     s1 * c[mi][ni][2]);
                atomicAdd(out + (size_t)(r0 + 8) * D_OUT + col + 1, s1 * c[mi][ni][3]);
            }
        }
    }
}

// ================= launch =================
extern "C" void kernel_launch(void* const* d_in, const int* in_sizes, int n_in,
                              void* d_out, int out_size) {
    const float* values = (const float*)d_in[0];
    const float* A      = (const float*)d_in[1];
    const float* W      = (const float*)d_in[2];
    const float* b      = (const float*)d_in[3];
    float* out = (float*)d_out;

    cudaMemsetAsync(out, 0, (size_t)out_size * sizeof(float));
    rowsum_kernel<<<N_NODES, 256>>>(A);
    fc_kernel<<<N_NODES / 32, 256>>>(values, W, b);
    cudaFuncSetAttribute(gemm_kernel, cudaFuncAttributeMaxDynamicSharedMemorySize, GEMM_SMEM);
    gemm_kernel<<<NCTA, 256, GEMM_SMEM>>>(A, out);
}